// round 2
// baseline (speedup 1.0000x reference)
#include <cuda_runtime.h>
#include <math_constants.h>

// Problem shape
#define BATCH 2
#define HEADS 16
#define SEQ   2048
#define EMB   1024
#define HDIM  64
#define BH    (BATCH*HEADS)     // 32
#define MROWS (BATCH*SEQ)       // 4096
#define NCOLS (3*EMB)           // 3072

// Scratch for Q/K/V in [b,h,d,p] layout (allowed: __device__ globals, no runtime alloc)
__device__ float g_q[BH*SEQ*HDIM];
__device__ float g_k[BH*SEQ*HDIM];
__device__ float g_v[BH*SEQ*HDIM];

// ======================= QKV projection GEMM =======================
// C[r][c] = sum_k X[r][k] * W[k][c] + bias[c], scattered into g_q/g_k/g_v
// Classic 128x128x8 SGEMM, 256 threads, 8x8 micro-tile, reg prefetch.
#define BM 128
#define BN 128
#define BK 8
#define SA_STRIDE 132   // padded stride for transposed A tile (conflict-free)

__global__ __launch_bounds__(256) void qkv_kernel(const float* __restrict__ X,
                                                  const float* __restrict__ W,
                                                  const float* __restrict__ bias)
{
    __shared__ float As[BK * SA_STRIDE];   // [k][m] transposed
    __shared__ float Bs[BK * BN];          // [k][n]

    const int tid = threadIdx.x;
    const int m0 = blockIdx.y * BM;
    const int n0 = blockIdx.x * BN;

    const int arow = tid >> 1;          // 0..127
    const int acol = (tid & 1) * 4;     // 0 or 4
    const int brow = tid >> 5;          // 0..7
    const int bcol = (tid & 31) * 4;    // 0..124

    const int tx = tid & 15;            // n groups of 8
    const int ty = tid >> 4;            // m groups of 8

    float acc[8][8];
    #pragma unroll
    for (int i = 0; i < 8; i++)
        #pragma unroll
        for (int j = 0; j < 8; j++) acc[i][j] = 0.f;

    // preload first k-tile into registers
    float4 a_reg = *(const float4*)(X + (m0 + arow) * EMB + acol);
    float4 b_reg = *(const float4*)(W + brow * NCOLS + n0 + bcol);

    const int NK = EMB / BK;  // 128
    for (int kt = 0; kt < NK; kt++) {
        // stage registers -> smem
        As[(acol + 0) * SA_STRIDE + arow] = a_reg.x;
        As[(acol + 1) * SA_STRIDE + arow] = a_reg.y;
        As[(acol + 2) * SA_STRIDE + arow] = a_reg.z;
        As[(acol + 3) * SA_STRIDE + arow] = a_reg.w;
        *(float4*)&Bs[brow * BN + bcol] = b_reg;
        __syncthreads();

        // prefetch next tile (hidden behind compute)
        if (kt + 1 < NK) {
            a_reg = *(const float4*)(X + (m0 + arow) * EMB + (kt + 1) * BK + acol);
            b_reg = *(const float4*)(W + ((kt + 1) * BK + brow) * NCOLS + n0 + bcol);
        }

        #pragma unroll
        for (int k = 0; k < BK; k++) {
            float4 a0 = *(float4*)&As[k * SA_STRIDE + ty * 8];
            float4 a1 = *(float4*)&As[k * SA_STRIDE + ty * 8 + 4];
            float4 b0 = *(float4*)&Bs[k * BN + tx * 8];
            float4 b1 = *(float4*)&Bs[k * BN + tx * 8 + 4];
            float a8[8] = {a0.x, a0.y, a0.z, a0.w, a1.x, a1.y, a1.z, a1.w};
            float b8[8] = {b0.x, b0.y, b0.z, b0.w, b1.x, b1.y, b1.z, b1.w};
            #pragma unroll
            for (int i = 0; i < 8; i++)
                #pragma unroll
                for (int j = 0; j < 8; j++)
                    acc[i][j] += a8[i] * b8[j];
        }
        __syncthreads();
    }

    // epilogue: add bias, scatter to q/k/v in [b,h,d,p]
    const int c0 = n0 + tx * 8;
    const int s  = c0 >> 10;           // 0:q 1:k 2:v (8-col group never crosses 64 boundary)
    const int h  = (c0 >> 6) & 15;
    const int pp = c0 & 63;
    float* dstbase = (s == 0) ? g_q : ((s == 1) ? g_k : g_v);

    float bia[8];
    #pragma unroll
    for (int j = 0; j < 8; j++) bia[j] = bias[c0 + j];

    #pragma unroll
    for (int i = 0; i < 8; i++) {
        int r    = m0 + ty * 8 + i;
        int bidx = r >> 11;            // /2048
        int d    = r & 2047;
        float* dst = dstbase + ((size_t)(bidx * HEADS + h) * SEQ + d) * HDIM + pp;
        float4 v0 = make_float4(acc[i][0] + bia[0], acc[i][1] + bia[1],
                                acc[i][2] + bia[2], acc[i][3] + bia[3]);
        float4 v1 = make_float4(acc[i][4] + bia[4], acc[i][5] + bia[5],
                                acc[i][6] + bia[6], acc[i][7] + bia[7]);
        *(float4*)dst       = v0;
        *(float4*)(dst + 4) = v1;
    }
}

// ======================= Flash attention =======================
// Per block: one (b,h), 32 query rows; loop KV in tiles of 64.
// 128 threads: tx = 0..15 (cols of 4), ty = 0..7 (rows of 4).
#define BR 32
#define BC 64
#define QSTR 36   // Qt / Pt row stride ([p][row] / [k][row])
#define KSTR 68   // Kt / Vs row stride

__global__ __launch_bounds__(128) void attn_kernel(float* __restrict__ out)
{
    __shared__ float Qt[HDIM * QSTR];    // [p][row]
    __shared__ float KPt[HDIM * KSTR];   // Kt: [p][col]; later aliased as Pt: [k][row] (QSTR)
    __shared__ float Vs[BC * KSTR];      // [k][pp]

    const int tid = threadIdx.x;
    const int tx = tid & 15;
    const int ty = tid >> 4;
    const int bh = blockIdx.y;
    const int q0 = blockIdx.x * BR;

    const float* Qg = g_q + ((size_t)bh * SEQ + q0) * HDIM;
    const float* Kg = g_k + (size_t)bh * SEQ * HDIM;
    const float* Vg = g_v + (size_t)bh * SEQ * HDIM;

    // load Q tile transposed: [p][row]
    for (int it = tid; it < BR * 16; it += 128) {
        int row = it >> 4;
        int p4  = (it & 15) * 4;
        float4 v = *(const float4*)(Qg + row * HDIM + p4);
        Qt[(p4 + 0) * QSTR + row] = v.x;
        Qt[(p4 + 1) * QSTR + row] = v.y;
        Qt[(p4 + 2) * QSTR + row] = v.z;
        Qt[(p4 + 3) * QSTR + row] = v.w;
    }

    float m_i[4], l_i[4], o_acc[4][4];
    #pragma unroll
    for (int i = 0; i < 4; i++) {
        m_i[i] = -CUDART_INF_F;
        l_i[i] = 0.f;
        #pragma unroll
        for (int j = 0; j < 4; j++) o_acc[i][j] = 0.f;
    }

    for (int j0 = 0; j0 < SEQ; j0 += BC) {
        // load K tile transposed: [p][col]
        for (int it = tid; it < BC * 16; it += 128) {
            int c  = it >> 4;
            int p4 = (it & 15) * 4;
            float4 v = *(const float4*)(Kg + (size_t)(j0 + c) * HDIM + p4);
            KPt[(p4 + 0) * KSTR + c] = v.x;
            KPt[(p4 + 1) * KSTR + c] = v.y;
            KPt[(p4 + 2) * KSTR + c] = v.z;
            KPt[(p4 + 3) * KSTR + c] = v.w;
        }
        // load V tile direct: [k][pp]
        for (int it = tid; it < BC * 16; it += 128) {
            int k   = it >> 4;
            int pp4 = (it & 15) * 4;
            *(float4*)&Vs[k * KSTR + pp4] =
                *(const float4*)(Vg + (size_t)(j0 + k) * HDIM + pp4);
        }
        __syncthreads();

        // S = Q K^T  (4x4 per thread)
        float sv[4][4];
        #pragma unroll
        for (int i = 0; i < 4; i++)
            #pragma unroll
            for (int j = 0; j < 4; j++) sv[i][j] = 0.f;

        #pragma unroll 8
        for (int p = 0; p < HDIM; p++) {
            float4 a = *(float4*)&Qt[p * QSTR + ty * 4];
            float4 b = *(float4*)&KPt[p * KSTR + tx * 4];
            float a4[4] = {a.x, a.y, a.z, a.w};
            float b4[4] = {b.x, b.y, b.z, b.w};
            #pragma unroll
            for (int i = 0; i < 4; i++)
                #pragma unroll
                for (int j = 0; j < 4; j++)
                    sv[i][j] += a4[i] * b4[j];
        }
        __syncthreads();   // all threads done reading Kt before Pt overwrites it

        // online softmax + write P (transposed, aliased over Kt)
        #pragma unroll
        for (int i = 0; i < 4; i++) {
            float mloc = fmaxf(fmaxf(sv[i][0], sv[i][1]), fmaxf(sv[i][2], sv[i][3]));
            #pragma unroll
            for (int o = 8; o >= 1; o >>= 1)
                mloc = fmaxf(mloc, __shfl_xor_sync(0xffffffffu, mloc, o, 16));
            float mn = fmaxf(m_i[i], mloc);
            float alpha = __expf(m_i[i] - mn);   // exp(-inf)=0 on first tile
            m_i[i] = mn;
            float rs = 0.f;
            #pragma unroll
            for (int j = 0; j < 4; j++) {
                float e = __expf(sv[i][j] - mn);
                sv[i][j] = e;
                rs += e;
            }
            #pragma unroll
            for (int o = 8; o >= 1; o >>= 1)
                rs += __shfl_xor_sync(0xffffffffu, rs, o, 16);
            l_i[i] = l_i[i] * alpha + rs;
            #pragma unroll
            for (int j = 0; j < 4; j++) o_acc[i][j] *= alpha;
            // Pt[k][row] = P, k = tx*4+j, row = ty*4+i
            #pragma unroll
            for (int j = 0; j < 4; j++)
                KPt[(tx * 4 + j) * QSTR + ty * 4 + i] = sv[i][j];
        }
        __syncthreads();

        // O += P V
        #pragma unroll 8
        for (int k = 0; k < BC; k++) {
            float4 a = *(float4*)&KPt[k * QSTR + ty * 4];
            float4 b = *(float4*)&Vs[k * KSTR + tx * 4];
            float a4[4] = {a.x, a.y, a.z, a.w};
            float b4[4] = {b.x, b.y, b.z, b.w};
            #pragma unroll
            for (int i = 0; i < 4; i++)
                #pragma unroll
                for (int j = 0; j < 4; j++)
                    o_acc[i][j] += a4[i] * b4[j];
        }
        __syncthreads();   // before next tile overwrites K/V/P
    }

    // normalize and write output: raw (B,H,D,p) layout == d_out
    #pragma unroll
    for (int i = 0; i < 4; i++) {
        float inv = 1.f / l_i[i];
        float4 v = make_float4(o_acc[i][0] * inv, o_acc[i][1] * inv,
                               o_acc[i][2] * inv, o_acc[i][3] * inv);
        *(float4*)(out + ((size_t)bh * SEQ + q0 + ty * 4 + i) * HDIM + tx * 4) = v;
    }
}

extern "C" void kernel_launch(void* const* d_in, const int* in_sizes, int n_in,
                              void* d_out, int out_size)
{
    const float* x    = (const float*)d_in[0];
    const float* Wqkv = (const float*)d_in[1];
    const float* bqkv = (const float*)d_in[2];
    float* out = (float*)d_out;

    qkv_kernel<<<dim3(NCOLS / BN, MROWS / BM), 256>>>(x, Wqkv, bqkv);
    attn_kernel<<<dim3(SEQ / BR, BH), 128>>>(out);
}